// round 16
// baseline (speedup 1.0000x reference)
#include <cuda_runtime.h>
#include <cuda_fp16.h>
#include <math.h>
#include <stdint.h>

// Problem constants (fixed shapes from reference setup_inputs)
#define NTOK   8192      // B*S = 2*4096
#define SEQ    4096
#define DMODEL 1024
#define NEXP   16
#define DBOT   256
#define DTASK  32
#define RQUOTA 64

#define NPART 256        // stats partial blocks per batch

// ================= device scratch =================
__device__ float  g_L[NTOK * NEXP];
__device__ float  g_gmask[NEXP * DBOT];
__device__ float  g_cs[NEXP];
__device__ float  g_base[2 * NEXP];
__device__ float  g_stats[4];
__device__ float  g_part[2 * NPART * 2];
// pre-split activations (fp16; Xl used only by router kernel)
__device__ __align__(16) __half g_Xh[NTOK * DMODEL];
__device__ __align__(16) __half g_Xl[NTOK * DMODEL];
__device__ __align__(16) __half g_Zh[NTOK * DBOT];
// GEMM1 B (fp16 high): W_down^T [256][1024]
__device__ __align__(16) __half g_B1T_h[256 * DMODEL];
// Wr^T [16][1024] fp16 high/low (router operand)
__device__ __align__(16) __half g_WrT_h[16 * DMODEL];
__device__ __align__(16) __half g_WrT_l[16 * DMODEL];
// GEMM2 B (fp16 high): W_up^T [1024][256]
__device__ __align__(16) __half g_B2T_h[DMODEL * DBOT];

// ================= helpers =================
__device__ __forceinline__ uint32_t smem_u32(const void* p) {
    uint32_t a;
    asm("{ .reg .u64 t; cvta.to.shared.u64 t, %1; cvt.u32.u64 %0, t; }" : "=r"(a) : "l"(p));
    return a;
}
__device__ __forceinline__ void cp16(uint32_t dst, const void* src) {
    asm volatile("cp.async.cg.shared.global [%0], [%1], 16;" :: "r"(dst), "l"(src));
}
#define CP_COMMIT() asm volatile("cp.async.commit_group;" ::: "memory")
#define CP_WAIT(n)  asm volatile("cp.async.wait_group %0;" :: "n"(n) : "memory")

#define LDSM4(d, addr) \
    asm volatile("ldmatrix.sync.aligned.m8n8.x4.shared.b16 {%0,%1,%2,%3}, [%4];" \
        : "=r"((d)[0]), "=r"((d)[1]), "=r"((d)[2]), "=r"((d)[3]) : "r"(addr))

__device__ __forceinline__ void mma16816(float* d, const uint32_t* a,
                                         const uint32_t* b) {
    asm volatile(
        "mma.sync.aligned.m16n8k16.row.col.f32.f16.f16.f32 "
        "{%0,%1,%2,%3}, {%4,%5,%6,%7}, {%8,%9}, {%0,%1,%2,%3};"
        : "+f"(d[0]), "+f"(d[1]), "+f"(d[2]), "+f"(d[3])
        : "r"(a[0]), "r"(a[1]), "r"(a[2]), "r"(a[3]), "r"(b[0]), "r"(b[1]));
}

__device__ __forceinline__ void split2h(float x, float y, uint32_t& h, uint32_t& l) {
    __half2 hh = __float22half2_rn(make_float2(x, y));
    float rx = x - __half2float(__low2half(hh));
    float ry = y - __half2float(__high2half(hh));
    __half2 ll = __float22half2_rn(make_float2(rx, ry));
    h = *reinterpret_cast<uint32_t*>(&hh);
    l = *reinterpret_cast<uint32_t*>(&ll);
}

__device__ __forceinline__ float gelu1(float h) {
    float inner = 0.7978845608028654f * (h + 0.044715f * h * h * h);
    return 0.5f * h * (1.f + tanhf(inner));
}

// ================= kernel 1: stats partials (fp32) + x split to fp16 h/l =================
__global__ void k_stats(const float* __restrict__ x) {
    int b = blockIdx.y;
    const float4* xb = reinterpret_cast<const float4*>(x + (size_t)b * SEQ * DMODEL);
    uint2* xh = reinterpret_cast<uint2*>(g_Xh + (size_t)b * SEQ * DMODEL);
    uint2* xl = reinterpret_cast<uint2*>(g_Xl + (size_t)b * SEQ * DMODEL);
    const int nvec = SEQ * DMODEL / 4;
    float s = 0.f, q = 0.f;
    for (int i = blockIdx.x * blockDim.x + threadIdx.x; i < nvec;
         i += gridDim.x * blockDim.x) {
        float4 v = xb[i];
        s += v.x + v.y + v.z + v.w;
        q += v.x * v.x + v.y * v.y + v.z * v.z + v.w * v.w;
        uint32_t h0, l0, h1, l1;
        split2h(v.x, v.y, h0, l0);
        split2h(v.z, v.w, h1, l1);
        xh[i] = make_uint2(h0, h1);
        xl[i] = make_uint2(l0, l1);
    }
    __shared__ float rs[256], rq[256];
    rs[threadIdx.x] = s; rq[threadIdx.x] = q;
    __syncthreads();
    for (int st = 128; st > 0; st >>= 1) {
        if (threadIdx.x < st) {
            rs[threadIdx.x] += rs[threadIdx.x + st];
            rq[threadIdx.x] += rq[threadIdx.x + st];
        }
        __syncthreads();
    }
    if (threadIdx.x == 0) {
        g_part[(b * NPART + blockIdx.x) * 2 + 0] = rs[0];
        g_part[(b * NPART + blockIdx.x) * 2 + 1] = rq[0];
    }
}

// ================= kernel 2: merged weight tsplit + setup =================
// bid 0..255: W_down -> B1T_h ; 256..287: Wr -> WrT_h/l ; 288..543: W_up -> B2T_h
// bid 544: stats finalize + router consts ; 545..560: topo expert masks
__global__ void k_tsplit_setup(const float* __restrict__ W_down,
                               const float* __restrict__ Wr,
                               const float* __restrict__ W_up,
                               const int* __restrict__ task_id,
                               const float* __restrict__ task_emb,
                               const float* __restrict__ br,
                               const float* __restrict__ topo) {
    int bid = blockIdx.x;
    int tid = threadIdx.x;
    if (bid < 544) {
        const float* in;
        __half *outh, *outl = nullptr;
        int R, C, c0, r0;
        if (bid < 256) {
            in = W_down; outh = g_B1T_h;
            R = DMODEL; C = DBOT;
            c0 = (bid & 7) * 32; r0 = (bid >> 3) * 32;
        } else if (bid < 288) {
            in = Wr; outh = g_WrT_h; outl = g_WrT_l;
            R = DMODEL; C = NEXP;
            c0 = 0; r0 = (bid - 256) * 32;
        } else {
            in = W_up; outh = g_B2T_h;
            R = DBOT; C = DMODEL;
            int idx = bid - 288;
            c0 = (idx & 31) * 32; r0 = (idx >> 5) * 32;
        }
        __shared__ float t[32][33];
        int tx = tid & 31, ty = tid >> 5;
#pragma unroll
        for (int i = 0; i < 32; i += 8) {
            int r = r0 + ty + i, c = c0 + tx;
            t[ty + i][tx] = (r < R && c < C) ? in[(size_t)r * C + c] : 0.f;
        }
        __syncthreads();
#pragma unroll
        for (int i = 0; i < 32; i += 8) {
            int c = c0 + ty + i, r = r0 + tx;
            if (c < C && r < R) {
                float v = t[tx][ty + i];
                __half h = __float2half_rn(v);
                outh[(size_t)c * R + r] = h;
                if (outl)
                    outl[(size_t)c * R + r] = __float2half_rn(v - __half2float(h));
            }
        }
    } else if (bid == 544) {
        __shared__ double rd[256];
        for (int b = 0; b < 2; b++) {
            double s = (double)g_part[(b * NPART + tid) * 2 + 0];
            double q = (double)g_part[(b * NPART + tid) * 2 + 1];
            rd[tid] = s; __syncthreads();
            for (int st = 128; st > 0; st >>= 1) {
                if (tid < st) rd[tid] += rd[tid + st];
                __syncthreads();
            }
            double S = rd[0]; __syncthreads();
            rd[tid] = q; __syncthreads();
            for (int st = 128; st > 0; st >>= 1) {
                if (tid < st) rd[tid] += rd[tid + st];
                __syncthreads();
            }
            double Q = rd[0]; __syncthreads();
            if (tid == 0) {
                const double cnt = (double)SEQ * DMODEL;
                double mu  = S / cnt;
                double var = Q / cnt - mu * mu;
                g_stats[b * 2 + 0] = (float)mu;
                g_stats[b * 2 + 1] = (float)(1.0 / sqrt(var + 1e-5));
            }
            __syncthreads();
        }
        {
            __shared__ float rf[256];
            int e = tid & 15, lane = tid >> 4;
            float p = 0.f;
            for (int d = lane; d < DMODEL; d += 16) p += Wr[d * NEXP + e];
            rf[tid] = p; __syncthreads();
            if (tid < 16) {
                float s2 = 0.f;
                for (int l = 0; l < 16; l++) s2 += rf[l * 16 + tid];
                g_cs[tid] = s2;
            }
            __syncthreads();
        }
        if (tid < 32) {
            int b = tid >> 4, e = tid & 15;
            int tI = task_id[b];
            float v = br[e];
            for (int t = 0; t < DTASK; t++)
                v += task_emb[tI * DTASK + t] * Wr[(DMODEL + t) * NEXP + e];
            g_base[b * NEXP + e] = v;
        }
    } else {
        int e = bid - 545;
        __shared__ float row[256];
        __shared__ float rs[256];
        row[tid] = topo[e * DBOT + tid];
        __syncthreads();
        float v = row[tid];
        int rank = 0;
#pragma unroll 16
        for (int i = 0; i < DBOT; i++) {
            float u = row[i];
            rank += (u > v) || (u == v && i < tid);
        }
        int sel = (rank < RQUOTA);
        rs[tid] = sel ? 1.f / (1.f + expf(-v)) : 0.f;
        __syncthreads();
        for (int st = 128; st > 0; st >>= 1) {
            if (tid < st) rs[tid] += rs[tid + st];
            __syncthreads();
        }
        float gate = rs[0] / (float)RQUOTA;
        g_gmask[e * DBOT + tid] = sel ? gate : 0.f;
    }
}

// pipeline wait with run-time remaining count
template <int STG>
__device__ __forceinline__ void cp_wait_rem(int rem) {
    int w = rem < STG - 2 ? rem : STG - 2;
    switch (w) {
        case 4: CP_WAIT(4); break;
        case 3: CP_WAIT(3); break;
        case 2: CP_WAIT(2); break;
        case 1: CP_WAIT(1); break;
        default: CP_WAIT(0); break;
    }
}

// ================= k_router: 32x16 tiles, 256 CTAs, 3-term fp16, 4-stage =================
// L[row0:+32, 0:16]; warps 0,1 compute (16 rows each), all warps load.
__global__ void __launch_bounds__(128, 4) k_router() {
    constexpr int SBYTES = 6144;    // Ah 2K | Al 2K | Bh 1K | Bl 1K
    constexpr int OFF_AL = 2048;
    constexpr int OFF_BH = 4096;
    constexpr int STG = 4;
    const int row0 = blockIdx.x * 32;

    extern __shared__ char smem[];
    const int tid = threadIdx.x;
    const int wm = tid >> 5, lane = tid & 31;

    float acc[2][4] = {};

    // A fill: 32 rows x 4 chunks x2 arrays = 256 cp16 -> 2/thread
    const int r4 = tid >> 2, j4 = tid & 3;            // r4 0..31
    const int v4 = (r4 >> 1) & 3;
    const uint32_t fill_off = (uint32_t)(r4 * 64 + (j4 ^ v4) * 16);
    // B fill: tid<64 -> Bh, 64..127 -> Bl (16 rows x 4 chunks each)
    const int t2 = tid & 63;
    const int rB = t2 >> 2, jB = t2 & 3;
    const int vB = (rB >> 1) & 3;
    const uint32_t bfill = (uint32_t)(rB * 64 + (jB ^ vB) * 16);
    const uint32_t sb = smem_u32(smem);

    const int ra = wm * 16 + (lane & 15);             // valid for wm<2
    const int ca = lane >> 4;
    const int va = (ra >> 1) & 3;
    const int rb = ((lane >> 4) << 3) + (lane & 7);
    const int cb = (lane >> 3) & 1;
    const int vb = (rb >> 1) & 3;
    const uint32_t a_base = (uint32_t)(ra * 64);
    const uint32_t b_base = (uint32_t)(rb * 64);

    const int nch = DMODEL >> 5;   // 32

#define ISSUE_R(ch) do { \
    const uint32_t _db = sb + ((ch) % STG) * SBYTES; \
    const int _k0 = (ch) * 32; \
    { \
        uint32_t d = _db + fill_off; \
        size_t ai = (size_t)(row0 + r4) * DMODEL + _k0 + j4 * 8; \
        cp16(d, g_Xh + ai); \
        cp16(d + OFF_AL, g_Xl + ai); \
    } \
    if (tid < 64) \
        cp16(_db + OFF_BH + bfill, g_WrT_h + ((size_t)rB * DMODEL + _k0 + jB * 8)); \
    else \
        cp16(_db + OFF_BH + 1024 + bfill, g_WrT_l + ((size_t)rB * DMODEL + _k0 + jB * 8)); \
    CP_COMMIT(); } while (0)

#pragma unroll
    for (int s = 0; s < STG - 1; s++) ISSUE_R(s);

    for (int ch = 0; ch < nch; ch++) {
        cp_wait_rem<STG>(nch - 1 - ch);
        __syncthreads();
        if (ch + STG - 1 < nch) ISSUE_R(ch + STG - 1);

        if (wm < 2) {
            const uint32_t ab = sb + (ch % STG) * SBYTES;
#pragma unroll
            for (int ks = 0; ks < 2; ks++) {
                const uint32_t aoff = ab + a_base + (uint32_t)(((ca + 2 * ks) ^ va) * 16);
                const uint32_t boff = ab + OFF_BH + b_base
                                    + (uint32_t)(((cb + 2 * ks) ^ vb) * 16);
                uint32_t ah[4], al[4], bb[4];
                LDSM4(ah, aoff);
                LDSM4(al, aoff + OFF_AL);
                LDSM4(bb, boff);
                mma16816(acc[0], ah, &bb[0]);
                mma16816(acc[1], ah, &bb[2]);
                mma16816(acc[0], al, &bb[0]);
                mma16816(acc[1], al, &bb[2]);
                LDSM4(bb, boff + 1024);
                mma16816(acc[0], ah, &bb[0]);
                mma16816(acc[1], ah, &bb[2]);
            }
        }
    }
#undef ISSUE_R

    if (wm >= 2) return;
    const int g = lane >> 2, tig = lane & 3;
    int r = row0 + wm * 16 + g;
#pragma unroll
    for (int nt = 0; nt < 2; nt++) {
        int col = nt * 8 + 2 * tig;
        *reinterpret_cast<float2*>(&g_L[(size_t)r * NEXP + col]) =
            make_float2(acc[nt][0], acc[nt][1]);
        *reinterpret_cast<float2*>(&g_L[(size_t)(r + 8) * NEXP + col]) =
            make_float2(acc[nt][2], acc[nt][3]);
    }
}

// ================= main GEMM body: 32x128 tile, 1-term fp16 =================
// MODE 0: store fp32 C (y). MODE 1: fused gelu+combine -> g_Zh fp16.
template <int MODE, int STG>
__device__ __forceinline__ void gemm_main(
    const __half* __restrict__ Ah, const __half* __restrict__ Bh,
    int K, int n0, int row0, float* __restrict__ C, int ldc,
    const int (*ssel)[2], const float (*swt)[2])
{
    constexpr int SBYTES = 10240;   // Ah 2K | Bh 8K
    constexpr int OFF_B = 2048;

    extern __shared__ char smem[];
    const int tid = threadIdx.x;
    const int wn = tid >> 5, lane = tid & 31;

    float acc[2][4][4] = {};

    const int r4 = tid >> 2, j4 = tid & 3;            // 32 rows x 4 chunks
    const int v4 = (r4 >> 1) & 3;
    const uint32_t fill_off = (uint32_t)(r4 * 64 + (j4 ^ v4) * 16);
    const uint32_t sb = smem_u32(smem);

    const int ra = lane & 15;
    const int ca = lane >> 4;
    const int va = (ra >> 1) & 3;
    const int rb = wn * 32 + ((lane >> 4) << 3) + (lane & 7);
    const int cb = (lane >> 3) & 1;
    const int vb = (rb >> 1) & 3;
    const uint32_t a_base = (uint32_t)(ra * 64);
    const uint32_t b_base = (uint32_t)(rb * 64);

    const int nch = K >> 5;

#define ISSUE_M(ch) do { \
    const uint32_t _db = sb + ((ch) % STG) * SBYTES; \
    const int _k0 = (ch) * 32; \
    cp16(_db + fill_off, Ah + ((size_t)(row0 + r4) * K + _k0 + j4 * 8)); \
    _Pragma("unroll") \
    for (int p = 0; p < 4; p++) { \
        uint32_t d = _db + OFF_B + (uint32_t)(p * 2048) + fill_off; \
        cp16(d, Bh + ((size_t)(n0 + p * 32 + r4) * K + _k0 + j4 * 8)); \
    } \
    CP_COMMIT(); } while (0)

#pragma unroll
    for (int s = 0; s < STG - 1; s++) ISSUE_M(s);

    for (int ch = 0; ch < nch; ch++) {
        cp_wait_rem<STG>(nch - 1 - ch);
        __syncthreads();
        if (ch + STG - 1 < nch) ISSUE_M(ch + STG - 1);

        const uint32_t ab = sb + (ch % STG) * SBYTES;
#pragma unroll
        for (int ks = 0; ks < 2; ks++) {
            const uint32_t aoff = ab + a_base + (uint32_t)(((ca + 2 * ks) ^ va) * 16);
            const uint32_t boff = ab + OFF_B + b_base
                                + (uint32_t)(((cb + 2 * ks) ^ vb) * 16);
            uint32_t ah[2][4], bb[4][2];
#pragma unroll
            for (int mt = 0; mt < 2; mt++)
                LDSM4(ah[mt], aoff + mt * 1024);
#pragma unroll
            for (int p = 0; p < 2; p++)
                LDSM4(&bb[2 * p][0], boff + p * 1024);
#pragma unroll
            for (int mt = 0; mt < 2; mt++)
#pragma unroll
                for (int nt = 0; nt < 4; nt++)
                    mma16816(acc[mt][nt], ah[mt], bb[nt]);
        }
    }
#undef ISSUE_M

    const int g = lane >> 2, tig = lane & 3;
#pragma unroll
    for (int mt = 0; mt < 2; mt++) {
        int lr = mt * 16 + g;
        int r = row0 + lr;
#pragma unroll
        for (int nt = 0; nt < 4; nt++) {
            int col = n0 + wn * 32 + nt * 8 + 2 * tig;
            if (MODE == 0) {
                *reinterpret_cast<float2*>(&C[(size_t)r * ldc + col]) =
                    make_float2(acc[mt][nt][0], acc[mt][nt][1]);
                *reinterpret_cast<float2*>(&C[(size_t)(r + 8) * ldc + col]) =
                    make_float2(acc[mt][nt][2], acc[mt][nt][3]);
            } else {
#pragma unroll
                for (int hh = 0; hh < 2; hh++) {
                    int lrr = lr + hh * 8;
                    int e0 = ssel[lrr][0], e1 = ssel[lrr][1];
                    float w0 = swt[lrr][0], w1 = swt[lrr][1];
                    float2 m0 = *reinterpret_cast<const float2*>(&g_gmask[e0 * DBOT + col]);
                    float2 m1 = *reinterpret_cast<const float2*>(&g_gmask[e1 * DBOT + col]);
                    float z0 = gelu1(acc[mt][nt][2 * hh + 0]) * (w0 * m0.x + w1 * m1.x);
                    float z1 = gelu1(acc[mt][nt][2 * hh + 1]) * (w0 * m0.y + w1 * m1.y);
                    __half2 zz = __float22half2_rn(make_float2(z0, z1));
                    *reinterpret_cast<__half2*>(&g_Zh[(size_t)(row0 + lrr) * DBOT + col]) = zz;
                }
            }
        }
    }
}

// GEMM1: routing prologue from g_L (32 rows), fused gelu epilogue -> g_Zh
__global__ void __launch_bounds__(128, 5) k_gemm1() {
    __shared__ int   ssel[32][2];
    __shared__ float swt[32][2];
    const int row0 = blockIdx.y * 32;
    if (threadIdx.x < 32) {
        int n = row0 + threadIdx.x;
        int b = n >> 12;
        float mu = g_stats[b * 2 + 0];
        float rstd = g_stats[b * 2 + 1];
        float best = -1e30f, sec = -1e30f;
        int i0 = 0, i1 = 0;
#pragma unroll
        for (int e = 0; e < NEXP; e++) {
            float l = rstd * (g_L[n * NEXP + e] - mu * g_cs[e]) + g_base[b * NEXP + e];
            if (l > best) { sec = best; i1 = i0; best = l; i0 = e; }
            else if (l > sec) { sec = l; i1 = e; }
        }
        float e1 = expf(sec - best);
        float inv = 1.f / (1.f + e1);
        ssel[threadIdx.x][0] = i0; ssel[threadIdx.x][1] = i1;
        swt[threadIdx.x][0] = inv; swt[threadIdx.x][1] = e1 * inv;
    }
    __syncthreads();
    gemm_main<1, 4>(g_Xh, g_B1T_h, DMODEL, blockIdx.x * 128, row0,
                    nullptr, 0, ssel, swt);
}
// GEMM2: plain fp32 store (32-row tiles too, grid 8x256)
__global__ void __launch_bounds__(128, 5) k_gemm2(float* __restrict__ y) {
    gemm_main<0, 4>(g_Zh, g_B2T_h, DBOT, blockIdx.x * 128, blockIdx.y * 32,
                    y, DMODEL, nullptr, nullptr);
}

// ================= launch =================
extern "C" void kernel_launch(void* const* d_in, const int* in_sizes, int n_in,
                              void* d_out, int out_size) {
    const float* x        = (const float*)d_in[0];
    const int*   task_id  = (const int*)d_in[1];
    const float* task_emb = (const float*)d_in[2];
    const float* Wr       = (const float*)d_in[3];
    const float* br       = (const float*)d_in[4];
    const float* W_down   = (const float*)d_in[5];
    const float* W_up     = (const float*)d_in[6];
    const float* topo     = (const float*)d_in[7];
    float* y = (float*)d_out;

    cudaFuncSetAttribute(k_router, cudaFuncAttributeMaxDynamicSharedMemorySize, 4 * 6144);
    cudaFuncSetAttribute(k_gemm1,  cudaFuncAttributeMaxDynamicSharedMemorySize, 4 * 10240);
    cudaFuncSetAttribute(k_gemm2,  cudaFuncAttributeMaxDynamicSharedMemorySize, 4 * 10240);

    k_stats<<<dim3(NPART, 2), 256>>>(x);                                   // 1
    k_tsplit_setup<<<561, 256>>>(W_down, Wr, W_up, task_id, task_emb, br, topo); // 2
    k_router<<<256, 128, 4 * 6144>>>();                                    // 3
    k_gemm1<<<dim3(2, 256), 128, 4 * 10240>>>();                           // 4 -> profiled
    k_gemm2<<<dim3(8, 256), 128, 4 * 10240>>>(y);                          // 5
}

// round 17
// speedup vs baseline: 1.0254x; 1.0254x over previous
#include <cuda_runtime.h>
#include <cuda_fp16.h>
#include <math.h>
#include <stdint.h>

// Problem constants (fixed shapes from reference setup_inputs)
#define NTOK   8192      // B*S = 2*4096
#define SEQ    4096
#define DMODEL 1024
#define NEXP   16
#define DBOT   256
#define DTASK  32
#define RQUOTA 64

#define NPART 256        // stats partial blocks per batch

// ================= device scratch =================
__device__ float  g_L[NTOK * NEXP];
__device__ float  g_gmask[NEXP * DBOT];
__device__ float  g_cs[NEXP];
__device__ float  g_base[2 * NEXP];
__device__ float  g_stats[4];
__device__ float  g_part[2 * NPART * 2];
// pre-split activations (fp16; Xl used only by router kernel)
__device__ __align__(16) __half g_Xh[NTOK * DMODEL];
__device__ __align__(16) __half g_Xl[NTOK * DMODEL];
__device__ __align__(16) __half g_Zh[NTOK * DBOT];
// GEMM1 B (fp16 high): W_down^T [256][1024]
__device__ __align__(16) __half g_B1T_h[256 * DMODEL];
// Wr^T [16][1024] fp16 high/low (router operand)
__device__ __align__(16) __half g_WrT_h[16 * DMODEL];
__device__ __align__(16) __half g_WrT_l[16 * DMODEL];
// GEMM2 B (fp16 high): W_up^T [1024][256]
__device__ __align__(16) __half g_B2T_h[DMODEL * DBOT];

// ================= helpers =================
__device__ __forceinline__ uint32_t smem_u32(const void* p) {
    uint32_t a;
    asm("{ .reg .u64 t; cvta.to.shared.u64 t, %1; cvt.u32.u64 %0, t; }" : "=r"(a) : "l"(p));
    return a;
}
__device__ __forceinline__ void cp16(uint32_t dst, const void* src) {
    asm volatile("cp.async.cg.shared.global [%0], [%1], 16;" :: "r"(dst), "l"(src));
}
#define CP_COMMIT() asm volatile("cp.async.commit_group;" ::: "memory")
#define CP_WAIT(n)  asm volatile("cp.async.wait_group %0;" :: "n"(n) : "memory")

#define LDSM4(d, addr) \
    asm volatile("ldmatrix.sync.aligned.m8n8.x4.shared.b16 {%0,%1,%2,%3}, [%4];" \
        : "=r"((d)[0]), "=r"((d)[1]), "=r"((d)[2]), "=r"((d)[3]) : "r"(addr))

__device__ __forceinline__ void mma16816(float* d, const uint32_t* a,
                                         const uint32_t* b) {
    asm volatile(
        "mma.sync.aligned.m16n8k16.row.col.f32.f16.f16.f32 "
        "{%0,%1,%2,%3}, {%4,%5,%6,%7}, {%8,%9}, {%0,%1,%2,%3};"
        : "+f"(d[0]), "+f"(d[1]), "+f"(d[2]), "+f"(d[3])
        : "r"(a[0]), "r"(a[1]), "r"(a[2]), "r"(a[3]), "r"(b[0]), "r"(b[1]));
}

__device__ __forceinline__ void split2h(float x, float y, uint32_t& h, uint32_t& l) {
    __half2 hh = __float22half2_rn(make_float2(x, y));
    float rx = x - __half2float(__low2half(hh));
    float ry = y - __half2float(__high2half(hh));
    __half2 ll = __float22half2_rn(make_float2(rx, ry));
    h = *reinterpret_cast<uint32_t*>(&hh);
    l = *reinterpret_cast<uint32_t*>(&ll);
}

__device__ __forceinline__ float gelu1(float h) {
    float inner = 0.7978845608028654f * (h + 0.044715f * h * h * h);
    return 0.5f * h * (1.f + tanhf(inner));
}

// ================= k_work: merged stats (blocks 0..511) + weight tsplit (512..1055) =================
__global__ void k_work(const float* __restrict__ x,
                       const float* __restrict__ W_down,
                       const float* __restrict__ Wr,
                       const float* __restrict__ W_up) {
    __shared__ __align__(16) float sh[32][33];   // 4.2KB, reused by both branches
    int bid = blockIdx.x;
    int tid = threadIdx.x;

    if (bid < 512) {
        // ---- stats partials + x split ----
        int b = bid >> 8;
        int part = bid & 255;
        const float4* xb = reinterpret_cast<const float4*>(x + (size_t)b * SEQ * DMODEL);
        uint2* xh = reinterpret_cast<uint2*>(g_Xh + (size_t)b * SEQ * DMODEL);
        uint2* xl = reinterpret_cast<uint2*>(g_Xl + (size_t)b * SEQ * DMODEL);
        const int nvec = SEQ * DMODEL / 4;
        float s = 0.f, q = 0.f;
        for (int i = part * 256 + tid; i < nvec; i += NPART * 256) {
            float4 v = xb[i];
            s += v.x + v.y + v.z + v.w;
            q += v.x * v.x + v.y * v.y + v.z * v.z + v.w * v.w;
            uint32_t h0, l0, h1, l1;
            split2h(v.x, v.y, h0, l0);
            split2h(v.z, v.w, h1, l1);
            xh[i] = make_uint2(h0, h1);
            xl[i] = make_uint2(l0, l1);
        }
        float* rs = &sh[0][0];        // 256 floats
        float* rq = &sh[8][0];        // 256 floats (disjoint region)
        rs[tid] = s; rq[tid] = q;
        __syncthreads();
        for (int st = 128; st > 0; st >>= 1) {
            if (tid < st) { rs[tid] += rs[tid + st]; rq[tid] += rq[tid + st]; }
            __syncthreads();
        }
        if (tid == 0) {
            g_part[(b * NPART + part) * 2 + 0] = rs[0];
            g_part[(b * NPART + part) * 2 + 1] = rq[0];
        }
    } else {
        // ---- weight transpose + fp16 split ----
        int tb = bid - 512;
        const float* in;
        __half *outh, *outl = nullptr;
        int R, C, c0, r0;
        if (tb < 256) {
            in = W_down; outh = g_B1T_h;
            R = DMODEL; C = DBOT;
            c0 = (tb & 7) * 32; r0 = (tb >> 3) * 32;
        } else if (tb < 288) {
            in = Wr; outh = g_WrT_h; outl = g_WrT_l;
            R = DMODEL; C = NEXP;
            c0 = 0; r0 = (tb - 256) * 32;
        } else {
            in = W_up; outh = g_B2T_h;
            R = DBOT; C = DMODEL;
            int idx = tb - 288;
            c0 = (idx & 31) * 32; r0 = (idx >> 5) * 32;
        }
        int tx = tid & 31, ty = tid >> 5;
#pragma unroll
        for (int i = 0; i < 32; i += 8) {
            int r = r0 + ty + i, c = c0 + tx;
            sh[ty + i][tx] = (r < R && c < C) ? in[(size_t)r * C + c] : 0.f;
        }
        __syncthreads();
#pragma unroll
        for (int i = 0; i < 32; i += 8) {
            int c = c0 + ty + i, r = r0 + tx;
            if (c < C && r < R) {
                float v = sh[tx][ty + i];
                __half h = __float2half_rn(v);
                outh[(size_t)c * R + r] = h;
                if (outl)
                    outl[(size_t)c * R + r] = __float2half_rn(v - __half2float(h));
            }
        }
    }
}

// ================= k_setup: block 0 = stats finalize/router consts; 1..16 = topo =================
__global__ void k_setup(const int* __restrict__ task_id,
                        const float* __restrict__ task_emb,
                        const float* __restrict__ Wr,
                        const float* __restrict__ br,
                        const float* __restrict__ topo) {
    int tid = threadIdx.x;
    if (blockIdx.x == 0) {
        __shared__ double rd[256];
        for (int b = 0; b < 2; b++) {
            double s = (double)g_part[(b * NPART + tid) * 2 + 0];
            double q = (double)g_part[(b * NPART + tid) * 2 + 1];
            rd[tid] = s; __syncthreads();
            for (int st = 128; st > 0; st >>= 1) {
                if (tid < st) rd[tid] += rd[tid + st];
                __syncthreads();
            }
            double S = rd[0]; __syncthreads();
            rd[tid] = q; __syncthreads();
            for (int st = 128; st > 0; st >>= 1) {
                if (tid < st) rd[tid] += rd[tid + st];
                __syncthreads();
            }
            double Q = rd[0]; __syncthreads();
            if (tid == 0) {
                const double cnt = (double)SEQ * DMODEL;
                double mu  = S / cnt;
                double var = Q / cnt - mu * mu;
                g_stats[b * 2 + 0] = (float)mu;
                g_stats[b * 2 + 1] = (float)(1.0 / sqrt(var + 1e-5));
            }
            __syncthreads();
        }
        {
            __shared__ float rf[256];
            int e = tid & 15, lane = tid >> 4;
            float p = 0.f;
            for (int d = lane; d < DMODEL; d += 16) p += Wr[d * NEXP + e];
            rf[tid] = p; __syncthreads();
            if (tid < 16) {
                float s2 = 0.f;
                for (int l = 0; l < 16; l++) s2 += rf[l * 16 + tid];
                g_cs[tid] = s2;
            }
            __syncthreads();
        }
        if (tid < 32) {
            int b = tid >> 4, e = tid & 15;
            int tI = task_id[b];
            float v = br[e];
            for (int t = 0; t < DTASK; t++)
                v += task_emb[tI * DTASK + t] * Wr[(DMODEL + t) * NEXP + e];
            g_base[b * NEXP + e] = v;
        }
    } else {
        int e = blockIdx.x - 1;
        __shared__ float row[256];
        __shared__ float rs[256];
        row[tid] = topo[e * DBOT + tid];
        __syncthreads();
        float v = row[tid];
        int rank = 0;
#pragma unroll 16
        for (int i = 0; i < DBOT; i++) {
            float u = row[i];
            rank += (u > v) || (u == v && i < tid);
        }
        int sel = (rank < RQUOTA);
        rs[tid] = sel ? 1.f / (1.f + expf(-v)) : 0.f;
        __syncthreads();
        for (int st = 128; st > 0; st >>= 1) {
            if (tid < st) rs[tid] += rs[tid + st];
            __syncthreads();
        }
        float gate = rs[0] / (float)RQUOTA;
        g_gmask[e * DBOT + tid] = sel ? gate : 0.f;
    }
}

// pipeline wait with run-time remaining count
template <int STG>
__device__ __forceinline__ void cp_wait_rem(int rem) {
    int w = rem < STG - 2 ? rem : STG - 2;
    switch (w) {
        case 4: CP_WAIT(4); break;
        case 3: CP_WAIT(3); break;
        case 2: CP_WAIT(2); break;
        case 1: CP_WAIT(1); break;
        default: CP_WAIT(0); break;
    }
}

// ================= k_router: 32x16 tiles, 256 CTAs, 3-term fp16, 4-stage (R16-proven) =================
__global__ void __launch_bounds__(128, 4) k_router() {
    constexpr int SBYTES = 6144;    // Ah 2K | Al 2K | Bh 1K | Bl 1K
    constexpr int OFF_AL = 2048;
    constexpr int OFF_BH = 4096;
    constexpr int STG = 4;
    const int row0 = blockIdx.x * 32;

    extern __shared__ char smem[];
    const int tid = threadIdx.x;
    const int wm = tid >> 5, lane = tid & 31;

    float acc[2][4] = {};

    const int r4 = tid >> 2, j4 = tid & 3;
    const int v4 = (r4 >> 1) & 3;
    const uint32_t fill_off = (uint32_t)(r4 * 64 + (j4 ^ v4) * 16);
    const int t2 = tid & 63;
    const int rB = t2 >> 2, jB = t2 & 3;
    const int vB = (rB >> 1) & 3;
    const uint32_t bfill = (uint32_t)(rB * 64 + (jB ^ vB) * 16);
    const uint32_t sb = smem_u32(smem);

    const int ra = wm * 16 + (lane & 15);
    const int ca = lane >> 4;
    const int va = (ra >> 1) & 3;
    const int rb = ((lane >> 4) << 3) + (lane & 7);
    const int cb = (lane >> 3) & 1;
    const int vb = (rb >> 1) & 3;
    const uint32_t a_base = (uint32_t)(ra * 64);
    const uint32_t b_base = (uint32_t)(rb * 64);

    const int nch = DMODEL >> 5;   // 32

#define ISSUE_R(ch) do { \
    const uint32_t _db = sb + ((ch) % STG) * SBYTES; \
    const int _k0 = (ch) * 32; \
    { \
        uint32_t d = _db + fill_off; \
        size_t ai = (size_t)(row0 + r4) * DMODEL + _k0 + j4 * 8; \
        cp16(d, g_Xh + ai); \
        cp16(d + OFF_AL, g_Xl + ai); \
    } \
    if (tid < 64) \
        cp16(_db + OFF_BH + bfill, g_WrT_h + ((size_t)rB * DMODEL + _k0 + jB * 8)); \
    else \
        cp16(_db + OFF_BH + 1024 + bfill, g_WrT_l + ((size_t)rB * DMODEL + _k0 + jB * 8)); \
    CP_COMMIT(); } while (0)

#pragma unroll
    for (int s = 0; s < STG - 1; s++) ISSUE_R(s);

    for (int ch = 0; ch < nch; ch++) {
        cp_wait_rem<STG>(nch - 1 - ch);
        __syncthreads();
        if (ch + STG - 1 < nch) ISSUE_R(ch + STG - 1);

        if (wm < 2) {
            const uint32_t ab = sb + (ch % STG) * SBYTES;
#pragma unroll
            for (int ks = 0; ks < 2; ks++) {
                const uint32_t aoff = ab + a_base + (uint32_t)(((ca + 2 * ks) ^ va) * 16);
                const uint32_t boff = ab + OFF_BH + b_base
                                    + (uint32_t)(((cb + 2 * ks) ^ vb) * 16);
                uint32_t ah[4], al[4], bb[4];
                LDSM4(ah, aoff);
                LDSM4(al, aoff + OFF_AL);
                LDSM4(bb, boff);
                mma16816(acc[0], ah, &bb[0]);
                mma16816(acc[1], ah, &bb[2]);
                mma16816(acc[0], al, &bb[0]);
                mma16816(acc[1], al, &bb[2]);
                LDSM4(bb, boff + 1024);
                mma16816(acc[0], ah, &bb[0]);
                mma16816(acc[1], ah, &bb[2]);
            }
        }
    }
#undef ISSUE_R

    if (wm >= 2) return;
    const int g = lane >> 2, tig = lane & 3;
    int r = row0 + wm * 16 + g;
#pragma unroll
    for (int nt = 0; nt < 2; nt++) {
        int col = nt * 8 + 2 * tig;
        *reinterpret_cast<float2*>(&g_L[(size_t)r * NEXP + col]) =
            make_float2(acc[nt][0], acc[nt][1]);
        *reinterpret_cast<float2*>(&g_L[(size_t)(r + 8) * NEXP + col]) =
            make_float2(acc[nt][2], acc[nt][3]);
    }
}

// ================= main GEMM body: 64x128 tile, 1-term fp16 (R15-proven) =================
// MODE 0: store fp32 C (y). MODE 1: fused gelu+combine -> g_Zh fp16.
template <int MODE, int STG>
__device__ __forceinline__ void gemm_main(
    const __half* __restrict__ Ah, const __half* __restrict__ Bh,
    int K, int n0, int row0, float* __restrict__ C, int ldc,
    const int (*ssel)[2], const float (*swt)[2])
{
    constexpr int SBYTES = 12288;   // Ah 4K | Bh 8K
    constexpr int OFF_B = 4096;

    extern __shared__ char smem[];
    const int tid = threadIdx.x;
    const int wn = tid >> 5, lane = tid & 31;

    float acc[4][4][4] = {};

    const int r4 = tid >> 2, j4 = tid & 3;
    const int v4 = (r4 >> 1) & 3;
    const uint32_t fill_off = (uint32_t)(r4 * 64 + (j4 ^ v4) * 16);
    const uint32_t sb = smem_u32(smem);

    const int ra = lane & 15;
    const int ca = lane >> 4;
    const int va = (ra >> 1) & 3;
    const int rb = wn * 32 + ((lane >> 4) << 3) + (lane & 7);
    const int cb = (lane >> 3) & 1;
    const int vb = (rb >> 1) & 3;
    const uint32_t a_base = (uint32_t)(ra * 64);
    const uint32_t b_base = (uint32_t)(rb * 64);

    const int nch = K >> 5;

#define ISSUE_M(ch) do { \
    const uint32_t _db = sb + ((ch) % STG) * SBYTES; \
    const int _k0 = (ch) * 32; \
    _Pragma("unroll") \
    for (int p = 0; p < 2; p++) { \
        uint32_t d = _db + (uint32_t)(p * 2048) + fill_off; \
        cp16(d, Ah + ((size_t)(row0 + p * 32 + r4) * K + _k0 + j4 * 8)); \
    } \
    _Pragma("unroll") \
    for (int p = 0; p < 4; p++) { \
        uint32_t d = _db + OFF_B + (uint32_t)(p * 2048) + fill_off; \
        cp16(d, Bh + ((size_t)(n0 + p * 32 + r4) * K + _k0 + j4 * 8)); \
    } \
    CP_COMMIT(); } while (0)

#pragma unroll
    for (int s = 0; s < STG - 1; s++) ISSUE_M(s);

    for (int ch = 0; ch < nch; ch++) {
        cp_wait_rem<STG>(nch - 1 - ch);
        __syncthreads();
        if (ch + STG - 1 < nch) ISSUE_M(ch + STG - 1);

        const uint32_t ab = sb + (ch % STG) * SBYTES;
#pragma unroll
        for (int ks = 0; ks < 2; ks++) {
            const uint32_t aoff = ab + a_base + (uint32_t)(((ca + 2 * ks) ^ va) * 16);
            const uint32_t boff = ab + OFF_B + b_base
                                + (uint32_t)(((cb + 2 * ks) ^ vb) * 16);
            uint32_t ah[4][4], bb[4][2];
#pragma unroll
            for (int mt = 0; mt < 4; mt++)
                LDSM4(ah[mt], aoff + mt * 1024);
#pragma unroll
            for (int p = 0; p < 2; p++)
                LDSM4(&bb[2 * p][0], boff + p * 1024);
#pragma unroll
            for (int mt = 0; mt < 4; mt++)
#pragma unroll
                for (int nt = 0; nt < 4; nt++)
                    mma16816(acc[mt][nt], ah[mt], bb[nt]);
        }
    }
#undef ISSUE_M

    const int g = lane >> 2, tig = lane & 3;
#pragma unroll
    for (int mt = 0; mt < 4; mt++) {
        int lr = mt * 16 + g;
        int r = row0 + lr;
#pragma unroll
        for (int nt = 0; nt < 4; nt++) {
            int col = n0 + wn * 32 + nt * 8 + 2 * tig;
            if (MODE == 0) {
                *reinterpret_cast<float2*>(&C[(size_t)r * ldc + col]) =
                    make_float2(acc[mt][nt][0], acc[mt][nt][1]);
                *reinterpret_cast<float2*>(&C[(size_t)(r + 8) * ldc + col]) =
                    make_float2(acc[mt][nt][2], acc[mt][nt][3]);
            } else {
#pragma unroll
                for (int hh = 0; hh < 2; hh++) {
                    int lrr = lr + hh * 8;
                    int e0 = ssel[lrr][0], e1 = ssel[lrr][1];
                    float w0 = swt[lrr][0], w1 = swt[lrr][1];
                    float2 m0 = *reinterpret_cast<const float2*>(&g_gmask[e0 * DBOT + col]);
                    float2 m1 = *reinterpret_cast<const float2*>(&g_gmask[e1 * DBOT + col]);
                    float z0 = gelu1(acc[mt][nt][2 * hh + 0]) * (w0 * m0.x + w1 * m1.x);
                    float z1 = gelu1(acc[mt][nt][2 * hh + 1]) * (w0 * m0.y + w1 * m1.y);
                    __half2 zz = __float22half2_rn(make_float2(z0, z1));
                    *reinterpret_cast<__half2*>(&g_Zh[(size_t)(row0 + lrr) * DBOT + col]) = zz;
                }
            }
        }
    }
}

// GEMM1: routing prologue from g_L (64 rows), fused gelu epilogue -> g_Zh
__global__ void __launch_bounds__(128, 3) k_gemm1() {
    __shared__ int   ssel[64][2];
    __shared__ float swt[64][2];
    const int row0 = blockIdx.y * 64;
    if (threadIdx.x < 64) {
        int n = row0 + threadIdx.x;
        int b = n >> 12;
        float mu = g_stats[b * 2 + 0];
        float rstd = g_stats[b * 2 + 1];
        float best = -1e30f, sec = -1e30f;
        int i0 = 0, i1 = 0;
#pragma unroll
        for (int e = 0; e < NEXP; e++) {
            float l = rstd * (g_L[n * NEXP + e] - mu * g_cs[e]) + g_base[b * NEXP + e];
            if (l > best) { sec = best; i1 = i0; best = l; i0 = e; }
            else if (l > sec) { sec = l; i1 = e; }
        }
        float e1 = expf(sec - best);
        float inv = 1.f / (1.f + e1);
        ssel[threadIdx.x][0] = i0; ssel[threadIdx.x][1] = i1;
        swt[threadIdx.x][0] = inv; swt[threadIdx.x][1] = e1 * inv;
    }
    __syncthreads();
    gemm_main<1, 6>(g_Xh, g_B1T_h, DMODEL, blockIdx.x * 128, row0,
                    nullptr, 0, ssel, swt);
}
// GEMM2: plain fp32 store (64-row tiles, grid 8x128)
__global__ void __launch_bounds__(128, 4) k_gemm2(float* __restrict__ y) {
    gemm_main<0, 4>(g_Zh, g_B2T_h, DBOT, blockIdx.x * 128, blockIdx.y * 64,
                    y, DMODEL, nullptr, nullptr);
}

// ================= launch =================
extern "C" void kernel_launch(void* const* d_in, const int* in_sizes, int n_in,
                              void* d_out, int out_size) {
    const float* x        = (const float*)d_in[0];
    const int*   task_id  = (const int*)d_in[1];
    const float* task_emb = (const float*)d_in[2];
    const float* Wr       = (const float*)d_in[3];
    const float* br       = (const float*)d_in[4];
    const float* W_down   = (const float*)d_in[5];
    const float* W_up     = (const float*)d_in[6];
    const float* topo     = (const float*)d_in[7];
    float* y = (float*)d_out;

    cudaFuncSetAttribute(k_router, cudaFuncAttributeMaxDynamicSharedMemorySize, 4 * 6144);
    cudaFuncSetAttribute(k_gemm1,  cudaFuncAttributeMaxDynamicSharedMemorySize, 73728);
    cudaFuncSetAttribute(k_gemm2,  cudaFuncAttributeMaxDynamicSharedMemorySize, 49152);

    k_work<<<1056, 256>>>(x, W_down, Wr, W_up);                 // 1 (stats ∥ tsplit)
    k_setup<<<17, 256>>>(task_id, task_emb, Wr, br, topo);      // 2
    k_router<<<256, 128, 4 * 6144>>>();                         // 3
    k_gemm1<<<dim3(2, 128), 128, 73728>>>();                    // 4 -> profiled
    k_gemm2<<<dim3(8, 128), 128, 49152>>>(y);                   // 5
}